// round 7
// baseline (speedup 1.0000x reference)
#include <cuda_runtime.h>
#include <cuda_bf16.h>
#include <cstdint>

// Problem constants
#define BB 2
#define SS 2048
#define DD 1024
#define HH 16
#define HD 64
#define N3 3072
#define MROWS 4096

// d_out layout
#define A_SZ   ((long long)BB * SS * DD)
#define P_HALF ((long long)BB * HH * SS * HD)
#define P_OFF  (A_SZ)
#define ATTN_OFF (A_SZ + 2 * P_HALF)

// Scratch (device globals)
__device__ float g_q[BB * HH * SS * HD];
__device__ float g_ah[MROWS * DD];
__device__ __nv_bfloat16 g_xhi[MROWS * DD], g_xlo[MROWS * DD];
__device__ __nv_bfloat16 g_wahi[N3 * DD],  g_walo[N3 * DD];    // w_attn^T [3072,1024]
__device__ __nv_bfloat16 g_wphi[DD * DD],  g_wplo[DD * DD];    // w_proj^T [1024,1024]
__device__ __nv_bfloat16 g_ahhi[MROWS * DD], g_ahlo[MROWS * DD];

// ====================== base-PTX helpers ====================================
__device__ __forceinline__ uint32_t smem_u32(const void* p) {
    uint32_t a;
    asm("{ .reg .u64 t; cvta.to.shared.u64 t, %1; cvt.u32.u64 %0, t; }"
        : "=r"(a) : "l"(p));
    return a;
}
__device__ __forceinline__ void ldsm4(uint32_t* r, uint32_t a) {
    asm volatile("ldmatrix.sync.aligned.m8n8.x4.shared.b16 {%0,%1,%2,%3}, [%4];"
                 : "=r"(r[0]), "=r"(r[1]), "=r"(r[2]), "=r"(r[3]) : "r"(a));
}
__device__ __forceinline__ void ldsm2(uint32_t* r, uint32_t a) {
    asm volatile("ldmatrix.sync.aligned.m8n8.x2.shared.b16 {%0,%1}, [%2];"
                 : "=r"(r[0]), "=r"(r[1]) : "r"(a));
}
__device__ __forceinline__ void ldsm2t(uint32_t* r, uint32_t a) {
    asm volatile("ldmatrix.sync.aligned.m8n8.x2.trans.shared.b16 {%0,%1}, [%2];"
                 : "=r"(r[0]), "=r"(r[1]) : "r"(a));
}
__device__ __forceinline__ void mma_bf16(float* d, const uint32_t* a, const uint32_t* b) {
    asm volatile("mma.sync.aligned.m16n8k16.row.col.f32.bf16.bf16.f32 "
                 "{%0,%1,%2,%3}, {%4,%5,%6,%7}, {%8,%9}, {%0,%1,%2,%3};"
                 : "+f"(d[0]), "+f"(d[1]), "+f"(d[2]), "+f"(d[3])
                 : "r"(a[0]), "r"(a[1]), "r"(a[2]), "r"(a[3]), "r"(b[0]), "r"(b[1]));
}
__device__ __forceinline__ void sp(float x, uint16_t& h, uint16_t& l) {
    __nv_bfloat16 bh = __float2bfloat16_rn(x);
    h = __bfloat16_as_ushort(bh);
    l = __bfloat16_as_ushort(__float2bfloat16_rn(x - __bfloat162float(bh)));
}
__device__ __forceinline__ uint32_t pk(uint16_t a, uint16_t b) {
    return (uint32_t)a | ((uint32_t)b << 16);
}

// ====================== bf16 split kernels ==================================
__global__ __launch_bounds__(256) void split_plain(const float* __restrict__ in,
                                                   __nv_bfloat16* __restrict__ hi,
                                                   __nv_bfloat16* __restrict__ lo, int n4) {
    int i = blockIdx.x * 256 + threadIdx.x;
    if (i >= n4) return;
    float4 v = ((const float4*)in)[i];
    uint16_t h0, h1, h2, h3, l0, l1, l2, l3;
    sp(v.x, h0, l0); sp(v.y, h1, l1); sp(v.z, h2, l2); sp(v.w, h3, l3);
    ((uint2*)hi)[i] = make_uint2(pk(h0, h1), pk(h2, h3));
    ((uint2*)lo)[i] = make_uint2(pk(l0, l1), pk(l2, l3));
}

// transpose split: in fp32 [1024 x N] row-major -> out bf16 [N x 1024]
__global__ __launch_bounds__(256) void split_T(const float* __restrict__ in,
                                               __nv_bfloat16* __restrict__ hi,
                                               __nv_bfloat16* __restrict__ lo, int N) {
    __shared__ float t[32][33];
    int nb = blockIdx.x * 32, kb = blockIdx.y * 32;
#pragma unroll
    for (int r = 0; r < 4; r++)
        t[threadIdx.y + r * 8][threadIdx.x] =
            in[(long long)(kb + threadIdx.y + r * 8) * N + nb + threadIdx.x];
    __syncthreads();
#pragma unroll
    for (int r = 0; r < 4; r++) {
        int n = nb + threadIdx.y + r * 8;
        float v = t[threadIdx.x][threadIdx.y + r * 8];
        uint16_t h, l;
        sp(v, h, l);
        long long o = (long long)n * 1024 + kb + threadIdx.x;
        hi[o] = __ushort_as_bfloat16(h);
        lo[o] = __ushort_as_bfloat16(l);
    }
}

// ====================== mma.sync GEMM (bf16x3) ==============================
// D[128,128] = A[128,1024] @ B[N,K]^T, A/B pre-split bf16 hi/lo, K-major.
#define GPB 144                      // padded row bytes (72 bf16)
#define GT_TILEB (128 * GPB)         // 18432
#define GEMM_SMEM (4 * GT_TILEB)     // 73728

template <int MODE>
__global__ __launch_bounds__(256) void gemm_mma(
    const __nv_bfloat16* __restrict__ Ahi, const __nv_bfloat16* __restrict__ Alo,
    const __nv_bfloat16* __restrict__ Bhi, const __nv_bfloat16* __restrict__ Blo,
    const float* __restrict__ bias, float* __restrict__ out) {
    extern __shared__ char sm[];
    const uint32_t sb = smem_u32(sm);
    const int tid = threadIdx.x;
    const int lane = tid & 31, warp = tid >> 5;
    const int wm = warp >> 1, wn = warp & 1;          // 4 x 2 warps
    const int qr = lane >> 2, qc2 = (lane & 3) * 2;
    const int nbase = blockIdx.x * 128, rbase = blockIdx.y * 128;

    float o[2][8][4];
#pragma unroll
    for (int a = 0; a < 2; a++)
#pragma unroll
        for (int b = 0; b < 8; b++)
#pragma unroll
            for (int c = 0; c < 4; c++) o[a][b][c] = 0.f;

    const int lr = tid >> 1, lc = (tid & 1) * 32;
    const long long aoff = (long long)(rbase + lr) * 1024 + lc;
    const long long boff = (long long)(nbase + lr) * 1024 + lc;
    uint4* dA0 = (uint4*)(sm + lr * GPB + lc * 2);
    uint4* dA1 = (uint4*)(sm + GT_TILEB + lr * GPB + lc * 2);
    uint4* dB0 = (uint4*)(sm + 2 * GT_TILEB + lr * GPB + lc * 2);
    uint4* dB1 = (uint4*)(sm + 3 * GT_TILEB + lr * GPB + lc * 2);

    for (int ks = 0; ks < 16; ks++) {
        __syncthreads();
        const int kb = ks * 64;
        const uint4* pAh = (const uint4*)(Ahi + aoff + kb);
        const uint4* pAl = (const uint4*)(Alo + aoff + kb);
        const uint4* pBh = (const uint4*)(Bhi + boff + kb);
        const uint4* pBl = (const uint4*)(Blo + boff + kb);
#pragma unroll
        for (int c = 0; c < 4; c++) {
            dA0[c] = pAh[c]; dA1[c] = pAl[c];
            dB0[c] = pBh[c]; dB1[c] = pBl[c];
        }
        __syncthreads();

#pragma unroll
        for (int k16 = 0; k16 < 4; k16++) {
            uint32_t ah[2][4], al[2][4];
#pragma unroll
            for (int mt = 0; mt < 2; mt++) {
                uint32_t r = wm * 32 + mt * 16 + (lane & 7) + ((lane >> 3) & 1) * 8;
                uint32_t c = k16 * 16 + (lane >> 4) * 8;
                uint32_t off = r * GPB + c * 2;
                ldsm4(ah[mt], sb + off);
                ldsm4(al[mt], sb + GT_TILEB + off);
            }
#pragma unroll
            for (int nt = 0; nt < 8; nt++) {
                uint32_t bh[2], bl[2];
                uint32_t n = wn * 64 + nt * 8 + (lane & 7);
                uint32_t c = k16 * 16 + ((lane >> 3) & 1) * 8;
                uint32_t off = n * GPB + c * 2;
                ldsm2(bh, sb + 2 * GT_TILEB + off);
                ldsm2(bl, sb + 3 * GT_TILEB + off);
#pragma unroll
                for (int mt = 0; mt < 2; mt++) {
                    mma_bf16(o[mt][nt], ah[mt], bh);
                    mma_bf16(o[mt][nt], ah[mt], bl);
                    mma_bf16(o[mt][nt], al[mt], bh);
                }
            }
        }
    }

    // epilogue
#pragma unroll
    for (int nt = 0; nt < 8; nt++) {
        const int cg = nbase + wn * 64 + nt * 8 + qc2;
        const float b0 = bias[cg], b1 = bias[cg + 1];
#pragma unroll
        for (int mt = 0; mt < 2; mt++) {
            int r0 = rbase + wm * 32 + mt * 16 + qr;
            int r1 = r0 + 8;
            float2 v0 = make_float2(o[mt][nt][0] + b0, o[mt][nt][1] + b1);
            float2 v1 = make_float2(o[mt][nt][2] + b0, o[mt][nt][3] + b1);
            if (MODE == 0) {
                int which = cg >> 10, d0 = cg & 1023;
                int hh = d0 >> 6, e0 = d0 & 63;
                float* dst = (which == 0) ? g_q
                           : (which == 1) ? (out + P_OFF) : (out + P_OFF + P_HALF);
                int b_0 = r0 >> 11, s_0 = r0 & 2047;
                int b_1 = r1 >> 11, s_1 = r1 & 2047;
                *(float2*)&dst[(((long long)(b_0 * HH + hh)) * SS + s_0) * HD + e0] = v0;
                *(float2*)&dst[(((long long)(b_1 * HH + hh)) * SS + s_1) * HD + e0] = v1;
            } else {
                *(float2*)&out[(long long)r0 * DD + cg] = v0;
                *(float2*)&out[(long long)r1 * DD + cg] = v1;
            }
        }
    }
}

// ====================== attention (mma.sync, 2-pass recompute) ==============
#define APB 144
#define AT_TILEB (64 * APB)          // 9216
#define ATTN_SMEM (6 * AT_TILEB + 256)

// convert 64x64 fp32 tile (row stride HD) -> bf16 hi/lo smem tiles
__device__ __forceinline__ void cvt_tile(const float* __restrict__ g,
                                         char* hi, char* lo, int tid) {
    const int r = tid >> 1, c0 = (tid & 1) * 32;
    const float4* src = (const float4*)(g + r * HD + c0);
    uint32_t* dh = (uint32_t*)(hi + r * APB + c0 * 2);
    uint32_t* dl = (uint32_t*)(lo + r * APB + c0 * 2);
#pragma unroll
    for (int i = 0; i < 8; i++) {
        float4 v = src[i];
        uint16_t h0, h1, h2, h3, l0, l1, l2, l3;
        sp(v.x, h0, l0); sp(v.y, h1, l1); sp(v.z, h2, l2); sp(v.w, h3, l3);
        dh[i * 2] = pk(h0, h1); dh[i * 2 + 1] = pk(h2, h3);
        dl[i * 2] = pk(l0, l1); dl[i * 2 + 1] = pk(l2, l3);
    }
}

__global__ __launch_bounds__(128) void attn_mma(float* __restrict__ out) {
    extern __shared__ char sm[];
    const uint32_t sb = smem_u32(sm);
    char* sQh = sm;
    char* sQl = sm + AT_TILEB;
    char* sKh = sm + 2 * AT_TILEB;
    char* sKl = sm + 3 * AT_TILEB;
    char* sVh = sm + 4 * AT_TILEB;
    char* sVl = sm + 5 * AT_TILEB;
    float* srinv = (float*)(sm + 6 * AT_TILEB);

    const int tid = threadIdx.x;
    const int lane = tid & 31, wm = tid >> 5;      // 4 warps, m16 each
    const int qr = lane >> 2, qc2 = (lane & 3) * 2;
    const int qt = blockIdx.x, h = blockIdx.y, b = blockIdx.z;
    const int qbase = qt * 64, bh_ = b * HH + h;
    const long long headoff = (long long)bh_ * SS * HD;
    const float* qg = g_q + headoff + (long long)qbase * HD;
    const float* kg = out + P_OFF + headoff;
    const float* vg = out + P_OFF + P_HALF + headoff;
    float* attn_out = out + ATTN_OFF + (long long)bh_ * SS * SS;

    cvt_tile(qg, sQh, sQl, tid);
    __syncthreads();

    // preload Q fragments (row-major A frags, m16 x k16 x 4 chunks)
    uint32_t qh[4][4], ql[4][4];
#pragma unroll
    for (int j = 0; j < 4; j++) {
        uint32_t r = wm * 16 + (lane & 7) + ((lane >> 3) & 1) * 8;
        uint32_t c = j * 16 + (lane >> 4) * 8;
        uint32_t off = r * APB + c * 2;
        ldsm4(qh[j], sb + off);
        ldsm4(ql[j], sb + AT_TILEB + off);
    }

    const int r0g = qbase + wm * 16 + qr;
    const int r1g = r0g + 8;

    // ---------------- pass A: rowsums ----------------
    float rs0 = 0.f, rs1 = 0.f;
    for (int kt = 0; kt <= qt; kt++) {
        __syncthreads();
        cvt_tile(kg + (long long)kt * 64 * HD, sKh, sKl, tid);
        __syncthreads();
#pragma unroll
        for (int nt = 0; nt < 8; nt++) {
            float s[4] = {0.f, 0.f, 0.f, 0.f};
#pragma unroll
            for (int j = 0; j < 4; j++) {
                uint32_t bh2[2], bl2[2];
                uint32_t n = nt * 8 + (lane & 7);
                uint32_t c = j * 16 + ((lane >> 3) & 1) * 8;
                uint32_t off = n * APB + c * 2;
                ldsm2(bh2, sb + 2 * AT_TILEB + off);
                ldsm2(bl2, sb + 3 * AT_TILEB + off);
                mma_bf16(s, qh[j], bh2);
                mma_bf16(s, qh[j], bl2);
                mma_bf16(s, ql[j], bh2);
            }
            const int cg = kt * 64 + nt * 8 + qc2;
            if (cg <= r0g)     rs0 += __expf(s[0] * 0.125f);
            if (cg + 1 <= r0g) rs0 += __expf(s[1] * 0.125f);
            if (cg <= r1g)     rs1 += __expf(s[2] * 0.125f);
            if (cg + 1 <= r1g) rs1 += __expf(s[3] * 0.125f);
        }
    }
    rs0 += __shfl_xor_sync(0xFFFFFFFFu, rs0, 1);
    rs0 += __shfl_xor_sync(0xFFFFFFFFu, rs0, 2);
    rs1 += __shfl_xor_sync(0xFFFFFFFFu, rs1, 1);
    rs1 += __shfl_xor_sync(0xFFFFFFFFu, rs1, 2);
    if ((lane & 3) == 0) {
        srinv[wm * 16 + qr] = 1.0f / rs0;
        srinv[wm * 16 + qr + 8] = 1.0f / rs1;
    }
    __syncthreads();
    const float ri0 = srinv[wm * 16 + qr];
    const float ri1 = srinv[wm * 16 + qr + 8];

    // ---------------- pass B: write attn + A@V ----------------
    float o[8][4];
#pragma unroll
    for (int a = 0; a < 8; a++)
#pragma unroll
        for (int c = 0; c < 4; c++) o[a][c] = 0.f;

    for (int kt = 0; kt <= qt; kt++) {
        __syncthreads();
        cvt_tile(kg + (long long)kt * 64 * HD, sKh, sKl, tid);
        cvt_tile(vg + (long long)kt * 64 * HD, sVh, sVl, tid);
        __syncthreads();

        uint32_t sah[4][4], sal[4][4];
#pragma unroll
        for (int nt = 0; nt < 8; nt++) {
            float s[4] = {0.f, 0.f, 0.f, 0.f};
#pragma unroll
            for (int j = 0; j < 4; j++) {
                uint32_t bh2[2], bl2[2];
                uint32_t n = nt * 8 + (lane & 7);
                uint32_t c = j * 16 + ((lane >> 3) & 1) * 8;
                uint32_t off = n * APB + c * 2;
                ldsm2(bh2, sb + 2 * AT_TILEB + off);
                ldsm2(bl2, sb + 3 * AT_TILEB + off);
                mma_bf16(s, qh[j], bh2);
                mma_bf16(s, qh[j], bl2);
                mma_bf16(s, ql[j], bh2);
            }
            const int cg = kt * 64 + nt * 8 + qc2;
            float e0 = (cg > r0g)     ? 0.f : __expf(s[0] * 0.125f) * ri0;
            float e1 = (cg + 1 > r0g) ? 0.f : __expf(s[1] * 0.125f) * ri0;
            float e2 = (cg > r1g)     ? 0.f : __expf(s[2] * 0.125f) * ri1;
            float e3 = (cg + 1 > r1g) ? 0.f : __expf(s[3] * 0.125f) * ri1;
            *(float2*)&attn_out[(long long)r0g * SS + cg] = make_float2(e0, e1);
            *(float2*)&attn_out[(long long)r1g * SS + cg] = make_float2(e2, e3);
            // build S fragments for AV (A row-major m16 x k16; k = key idx)
            uint16_t h0, h1, h2, h3, l0, l1, l2, l3;
            sp(e0, h0, l0); sp(e1, h1, l1); sp(e2, h2, l2); sp(e3, h3, l3);
            const int j = nt >> 1, half = (nt & 1) * 2;
            sah[j][half]     = pk(h0, h1); sah[j][half + 1] = pk(h2, h3);
            sal[j][half]     = pk(l0, l1); sal[j][half + 1] = pk(l2, l3);
        }
#pragma unroll
        for (int j = 0; j < 4; j++) {
#pragma unroll
            for (int nt2 = 0; nt2 < 8; nt2++) {
                uint32_t vh2[2], vl2[2];
                uint32_t key = j * 16 + ((lane >> 3) & 1) * 8 + (lane & 7);
                uint32_t off = key * APB + nt2 * 16;   // nt2*8 bf16 = 16B
                ldsm2t(vh2, sb + 4 * AT_TILEB + off);
                ldsm2t(vl2, sb + 5 * AT_TILEB + off);
                mma_bf16(o[nt2], sah[j], vh2);
                mma_bf16(o[nt2], sah[j], vl2);
                mma_bf16(o[nt2], sal[j], vh2);
            }
        }
    }

    // write merged-head output
#pragma unroll
    for (int nt2 = 0; nt2 < 8; nt2++) {
        const int col = h * 64 + nt2 * 8 + qc2;
        const long long gr0 = (long long)(b * SS + qbase + wm * 16 + qr);
        *(float2*)&g_ah[gr0 * DD + col] = make_float2(o[nt2][0], o[nt2][1]);
        *(float2*)&g_ah[(gr0 + 8) * DD + col] = make_float2(o[nt2][2], o[nt2][3]);
    }
}

// ====================== upper-triangle zero fill ============================
__global__ __launch_bounds__(256) void attn_fill(float* __restrict__ out) {
    const int tid = threadIdx.x;
    const int qt = blockIdx.x, bh = blockIdx.y;
    const int Lc = (qt + 1) * 64;
    const int per4 = (SS - Lc) >> 2;
    if (per4 == 0) return;
    float* base = out + ATTN_OFF + (long long)bh * SS * SS + (long long)qt * 64 * SS;
    const float4 z = make_float4(0.f, 0.f, 0.f, 0.f);
    for (int i = tid; i < 64 * per4; i += 256) {
        int r = i / per4;
        int c = Lc + (i - r * per4) * 4;
        *(float4*)&base[(long long)r * SS + c] = z;
    }
}

// ====================== launch ==============================================
extern "C" void kernel_launch(void* const* d_in, const int* in_sizes, int n_in,
                              void* d_out, int out_size) {
    const float* x      = (const float*)d_in[0];
    const float* w_attn = (const float*)d_in[1];
    const float* b_attn = (const float*)d_in[2];
    const float* w_proj = (const float*)d_in[3];
    const float* b_proj = (const float*)d_in[4];
    float* out = (float*)d_out;

    __nv_bfloat16 *xhi, *xlo, *wahi, *walo, *wphi, *wplo, *ahhi, *ahlo;
    float* gah;
    cudaGetSymbolAddress((void**)&xhi,  g_xhi);
    cudaGetSymbolAddress((void**)&xlo,  g_xlo);
    cudaGetSymbolAddress((void**)&wahi, g_wahi);
    cudaGetSymbolAddress((void**)&walo, g_walo);
    cudaGetSymbolAddress((void**)&wphi, g_wphi);
    cudaGetSymbolAddress((void**)&wplo, g_wplo);
    cudaGetSymbolAddress((void**)&ahhi, g_ahhi);
    cudaGetSymbolAddress((void**)&ahlo, g_ahlo);
    cudaGetSymbolAddress((void**)&gah,  g_ah);

    cudaFuncSetAttribute(gemm_mma<0>, cudaFuncAttributeMaxDynamicSharedMemorySize, GEMM_SMEM);
    cudaFuncSetAttribute(gemm_mma<1>, cudaFuncAttributeMaxDynamicSharedMemorySize, GEMM_SMEM);
    cudaFuncSetAttribute(attn_mma, cudaFuncAttributeMaxDynamicSharedMemorySize, ATTN_SMEM);

    // 0) split inputs (weights transposed to [N,K])
    split_plain<<<(MROWS * DD / 4 + 255) / 256, 256>>>(x, xhi, xlo, MROWS * DD / 4);
    split_T<<<dim3(N3 / 32, DD / 32), dim3(32, 8)>>>(w_attn, wahi, walo, N3);
    split_T<<<dim3(DD / 32, DD / 32), dim3(32, 8)>>>(w_proj, wphi, wplo, DD);

    // 1) QKV projection -> g_q + present(k,v)
    gemm_mma<0><<<dim3(N3 / 128, MROWS / 128), 256, GEMM_SMEM>>>(xhi, xlo, wahi, walo, b_attn, out);

    // 2) attention -> normalized attn region + g_ah
    attn_mma<<<dim3(SS / 64, HH, BB), 128, ATTN_SMEM>>>(out);

    // 3) zero-fill strictly-upper attn region
    attn_fill<<<dim3(SS / 64, BB * HH), 256>>>(out);

    // 4) output projection
    split_plain<<<(MROWS * DD / 4 + 255) / 256, 256>>>(gah, ahhi, ahlo, MROWS * DD / 4);
    gemm_mma<1><<<dim3(DD / 128, MROWS / 128), 256, GEMM_SMEM>>>(ahhi, ahlo, wphi, wplo, b_proj, out);
}

// round 8
// speedup vs baseline: 1.3287x; 1.3287x over previous
#include <cuda_runtime.h>
#include <cuda_bf16.h>
#include <cstdint>

// Problem constants
#define BB 2
#define SS 2048
#define DD 1024
#define HH 16
#define HD 64
#define N3 3072
#define MROWS 4096

// d_out layout
#define A_SZ   ((long long)BB * SS * DD)
#define P_HALF ((long long)BB * HH * SS * HD)
#define P_OFF  (A_SZ)
#define ATTN_OFF (A_SZ + 2 * P_HALF)

// Scratch (device globals)
__device__ __nv_bfloat16 g_xhi[MROWS * DD], g_xlo[MROWS * DD];
__device__ __nv_bfloat16 g_wahi[N3 * DD],  g_walo[N3 * DD];    // w_attn^T [3072,1024]
__device__ __nv_bfloat16 g_wphi[DD * DD],  g_wplo[DD * DD];    // w_proj^T [1024,1024]
__device__ __nv_bfloat16 g_ahhi[MROWS * DD], g_ahlo[MROWS * DD];
// q/k/v in [B,H,S,hd], bf16 hi/lo (written by qkv epilogue)
#define QKV_N (BB * HH * SS * HD)
__device__ __nv_bfloat16 g_qh[QKV_N], g_ql[QKV_N];
__device__ __nv_bfloat16 g_kh[QKV_N], g_kl[QKV_N];
__device__ __nv_bfloat16 g_vh[QKV_N], g_vl[QKV_N];

// ====================== base-PTX helpers ====================================
__device__ __forceinline__ uint32_t smem_u32(const void* p) {
    uint32_t a;
    asm("{ .reg .u64 t; cvta.to.shared.u64 t, %1; cvt.u32.u64 %0, t; }"
        : "=r"(a) : "l"(p));
    return a;
}
__device__ __forceinline__ void cpa16(uint32_t s, const void* g) {
    asm volatile("cp.async.cg.shared.global [%0], [%1], 16;" :: "r"(s), "l"(g));
}
#define CP_COMMIT() asm volatile("cp.async.commit_group;" ::: "memory")
#define CP_WAIT(n)  asm volatile("cp.async.wait_group %0;" :: "n"(n) : "memory")

__device__ __forceinline__ void ldsm4(uint32_t* r, uint32_t a) {
    asm volatile("ldmatrix.sync.aligned.m8n8.x4.shared.b16 {%0,%1,%2,%3}, [%4];"
                 : "=r"(r[0]), "=r"(r[1]), "=r"(r[2]), "=r"(r[3]) : "r"(a));
}
__device__ __forceinline__ void ldsm2(uint32_t* r, uint32_t a) {
    asm volatile("ldmatrix.sync.aligned.m8n8.x2.shared.b16 {%0,%1}, [%2];"
                 : "=r"(r[0]), "=r"(r[1]) : "r"(a));
}
__device__ __forceinline__ void ldsm2t(uint32_t* r, uint32_t a) {
    asm volatile("ldmatrix.sync.aligned.m8n8.x2.trans.shared.b16 {%0,%1}, [%2];"
                 : "=r"(r[0]), "=r"(r[1]) : "r"(a));
}
__device__ __forceinline__ void mma_bf16(float* d, const uint32_t* a, const uint32_t* b) {
    asm volatile("mma.sync.aligned.m16n8k16.row.col.f32.bf16.bf16.f32 "
                 "{%0,%1,%2,%3}, {%4,%5,%6,%7}, {%8,%9}, {%0,%1,%2,%3};"
                 : "+f"(d[0]), "+f"(d[1]), "+f"(d[2]), "+f"(d[3])
                 : "r"(a[0]), "r"(a[1]), "r"(a[2]), "r"(a[3]), "r"(b[0]), "r"(b[1]));
}
__device__ __forceinline__ void sp(float x, uint16_t& h, uint16_t& l) {
    __nv_bfloat16 bh = __float2bfloat16_rn(x);
    h = __bfloat16_as_ushort(bh);
    l = __bfloat16_as_ushort(__float2bfloat16_rn(x - __bfloat162float(bh)));
}
__device__ __forceinline__ uint32_t pk(uint16_t a, uint16_t b) {
    return (uint32_t)a | ((uint32_t)b << 16);
}

// ====================== bf16 split kernels ==================================
__global__ __launch_bounds__(256) void split_plain(const float* __restrict__ in,
                                                   __nv_bfloat16* __restrict__ hi,
                                                   __nv_bfloat16* __restrict__ lo, int n4) {
    int i = blockIdx.x * 256 + threadIdx.x;
    if (i >= n4) return;
    float4 v = ((const float4*)in)[i];
    uint16_t h0, h1, h2, h3, l0, l1, l2, l3;
    sp(v.x, h0, l0); sp(v.y, h1, l1); sp(v.z, h2, l2); sp(v.w, h3, l3);
    ((uint2*)hi)[i] = make_uint2(pk(h0, h1), pk(h2, h3));
    ((uint2*)lo)[i] = make_uint2(pk(l0, l1), pk(l2, l3));
}

__global__ __launch_bounds__(256) void split_T(const float* __restrict__ in,
                                               __nv_bfloat16* __restrict__ hi,
                                               __nv_bfloat16* __restrict__ lo, int N) {
    __shared__ float t[32][33];
    int nb = blockIdx.x * 32, kb = blockIdx.y * 32;
#pragma unroll
    for (int r = 0; r < 4; r++)
        t[threadIdx.y + r * 8][threadIdx.x] =
            in[(long long)(kb + threadIdx.y + r * 8) * N + nb + threadIdx.x];
    __syncthreads();
#pragma unroll
    for (int r = 0; r < 4; r++) {
        int n = nb + threadIdx.y + r * 8;
        float v = t[threadIdx.x][threadIdx.y + r * 8];
        uint16_t h, l;
        sp(v, h, l);
        long long o = (long long)n * 1024 + kb + threadIdx.x;
        hi[o] = __ushort_as_bfloat16(h);
        lo[o] = __ushort_as_bfloat16(l);
    }
}

// ====================== pipelined mma.sync GEMM (bf16x3) ====================
#define GPB 144
#define GT_TILEB (128 * GPB)           // 18432
#define GT_STAGEB (4 * GT_TILEB)       // 73728
#define GEMM_SMEM (2 * GT_STAGEB)      // 147456

template <int MODE>
__global__ __launch_bounds__(256) void gemm_mma(
    const __nv_bfloat16* __restrict__ Ahi, const __nv_bfloat16* __restrict__ Alo,
    const __nv_bfloat16* __restrict__ Bhi, const __nv_bfloat16* __restrict__ Blo,
    const float* __restrict__ bias, float* __restrict__ out) {
    extern __shared__ char smm[];
    const uint32_t sb = smem_u32(smm);
    const int tid = threadIdx.x;
    const int lane = tid & 31, warp = tid >> 5;
    const int wm = warp >> 1, wn = warp & 1;
    const int qr = lane >> 2, qc2 = (lane & 3) * 2;
    const int nbase = blockIdx.x * 128, rbase = blockIdx.y * 128;

    float o[2][8][4];
#pragma unroll
    for (int a = 0; a < 2; a++)
#pragma unroll
        for (int b = 0; b < 8; b++)
#pragma unroll
            for (int c = 0; c < 4; c++) o[a][b][c] = 0.f;

    // per-thread load mapping: 4 chunks of 16B per tile, 4 tiles
    const int lr_ = tid >> 3;          // base row group
    const char* srcs[4] = {
        (const char*)(Ahi + (long long)rbase * 1024),
        (const char*)(Alo + (long long)rbase * 1024),
        (const char*)(Bhi + (long long)nbase * 1024),
        (const char*)(Blo + (long long)nbase * 1024)};

    // prologue: load stage 0
#pragma unroll
    for (int t = 0; t < 4; t++)
#pragma unroll
        for (int i = 0; i < 4; i++) {
            int idx = tid + i * 256;
            int r = idx >> 3, c = idx & 7;
            cpa16(sb + t * GT_TILEB + r * GPB + c * 16,
                  srcs[t] + (long long)r * 2048 + c * 16);
        }
    CP_COMMIT();

    for (int ks = 0; ks < 16; ks++) {
        const int st = ks & 1;
        if (ks + 1 < 16) {
            const int kboff = (ks + 1) * 128;   // bytes into K
            const uint32_t dstb = sb + ((ks + 1) & 1) * GT_STAGEB;
#pragma unroll
            for (int t = 0; t < 4; t++)
#pragma unroll
                for (int i = 0; i < 4; i++) {
                    int idx = tid + i * 256;
                    int r = idx >> 3, c = idx & 7;
                    cpa16(dstb + t * GT_TILEB + r * GPB + c * 16,
                          srcs[t] + (long long)r * 2048 + kboff + c * 16);
                }
            CP_COMMIT();
            CP_WAIT(1);
        } else {
            CP_WAIT(0);
        }
        __syncthreads();

        const uint32_t base = sb + st * GT_STAGEB;
#pragma unroll
        for (int k16 = 0; k16 < 4; k16++) {
            uint32_t ah[2][4], al[2][4];
#pragma unroll
            for (int mt = 0; mt < 2; mt++) {
                uint32_t r = wm * 32 + mt * 16 + (lane & 7) + ((lane >> 3) & 1) * 8;
                uint32_t c = k16 * 16 + (lane >> 4) * 8;
                uint32_t off = r * GPB + c * 2;
                ldsm4(ah[mt], base + off);
                ldsm4(al[mt], base + GT_TILEB + off);
            }
#pragma unroll
            for (int nt = 0; nt < 8; nt++) {
                uint32_t bh2[2], bl2[2];
                uint32_t n = wn * 64 + nt * 8 + (lane & 7);
                uint32_t c = k16 * 16 + ((lane >> 3) & 1) * 8;
                uint32_t off = n * GPB + c * 2;
                ldsm2(bh2, base + 2 * GT_TILEB + off);
                ldsm2(bl2, base + 3 * GT_TILEB + off);
#pragma unroll
                for (int mt = 0; mt < 2; mt++) {
                    mma_bf16(o[mt][nt], ah[mt], bh2);
                    mma_bf16(o[mt][nt], ah[mt], bl2);
                    mma_bf16(o[mt][nt], al[mt], bh2);
                }
            }
        }
        __syncthreads();
    }
    (void)lr_;

    // epilogue
#pragma unroll
    for (int nt = 0; nt < 8; nt++) {
        const int cg = nbase + wn * 64 + nt * 8 + qc2;
        const float b0 = bias[cg], b1 = bias[cg + 1];
#pragma unroll
        for (int mt = 0; mt < 2; mt++) {
            int r0 = rbase + wm * 32 + mt * 16 + qr;
            int r1 = r0 + 8;
            float2 v0 = make_float2(o[mt][nt][0] + b0, o[mt][nt][1] + b1);
            float2 v1 = make_float2(o[mt][nt][2] + b0, o[mt][nt][3] + b1);
            if (MODE == 0) {
                int which = cg >> 10, d0 = cg & 1023;
                int hh = d0 >> 6, e0 = d0 & 63;
                int b_0 = r0 >> 11, s_0 = r0 & 2047;
                int b_1 = r1 >> 11, s_1 = r1 & 2047;
                long long i0 = (((long long)(b_0 * HH + hh)) * SS + s_0) * HD + e0;
                long long i1 = (((long long)(b_1 * HH + hh)) * SS + s_1) * HD + e0;
                uint16_t h0, h1, h2, h3, l0, l1, l2, l3;
                sp(v0.x, h0, l0); sp(v0.y, h1, l1);
                sp(v1.x, h2, l2); sp(v1.y, h3, l3);
                if (which == 0) {
                    *(uint32_t*)&g_qh[i0] = pk(h0, h1); *(uint32_t*)&g_ql[i0] = pk(l0, l1);
                    *(uint32_t*)&g_qh[i1] = pk(h2, h3); *(uint32_t*)&g_ql[i1] = pk(l2, l3);
                } else if (which == 1) {
                    *(float2*)&out[P_OFF + i0] = v0;
                    *(float2*)&out[P_OFF + i1] = v1;
                    *(uint32_t*)&g_kh[i0] = pk(h0, h1); *(uint32_t*)&g_kl[i0] = pk(l0, l1);
                    *(uint32_t*)&g_kh[i1] = pk(h2, h3); *(uint32_t*)&g_kl[i1] = pk(l2, l3);
                } else {
                    *(float2*)&out[P_OFF + P_HALF + i0] = v0;
                    *(float2*)&out[P_OFF + P_HALF + i1] = v1;
                    *(uint32_t*)&g_vh[i0] = pk(h0, h1); *(uint32_t*)&g_vl[i0] = pk(l0, l1);
                    *(uint32_t*)&g_vh[i1] = pk(h2, h3); *(uint32_t*)&g_vl[i1] = pk(l2, l3);
                }
            } else {
                *(float2*)&out[(long long)r0 * DD + cg] = v0;
                *(float2*)&out[(long long)r1 * DD + cg] = v1;
            }
        }
    }
}

// ====================== attention (pipelined, 128-row Q tiles) ==============
#define APB 144
#define QT_B (128 * APB)               // 18432
#define KT_B (64 * APB)                // 9216
#define KSTAGE (4 * KT_B)              // 36864: Khi,Klo,Vhi,Vlo
#define KBASE (2 * QT_B)               // 36864
#define ATTN_SMEM (2 * QT_B + 2 * KSTAGE)   // 110592

__global__ __launch_bounds__(256) void attn_mma(float* __restrict__ out) {
    extern __shared__ char smm[];
    const uint32_t sb = smem_u32(smm);
    const int tid = threadIdx.x;
    const int lane = tid & 31, wm = tid >> 5;        // 8 warps x 16 q-rows
    const int qr = lane >> 2, qc2 = (lane & 3) * 2;
    const int qt = (gridDim.x - 1) - blockIdx.x;     // heavy tiles first
    const int h = blockIdx.y, b = blockIdx.z;
    const int qbase = qt * 128;
    const int bh_ = b * HH + h;
    const long long hoff = (long long)bh_ * SS * HD;
    const char* qhg = (const char*)(g_qh + hoff + (long long)qbase * HD);
    const char* qlg = (const char*)(g_ql + hoff + (long long)qbase * HD);
    const char* khg = (const char*)(g_kh + hoff);
    const char* klg = (const char*)(g_kl + hoff);
    const char* vhg = (const char*)(g_vh + hoff);
    const char* vlg = (const char*)(g_vl + hoff);
    float* attn_out = out + ATTN_OFF + (long long)bh_ * SS * SS;
    const int nkt = 2 * qt + 2;

    // load Q hi/lo (each 128 rows x 128B contiguous)
#pragma unroll
    for (int i = 0; i < 4; i++) {
        int idx = tid + i * 256;
        int r = idx >> 3, c = idx & 7;
        cpa16(sb + r * APB + c * 16, qhg + idx * 16);
        cpa16(sb + QT_B + r * APB + c * 16, qlg + idx * 16);
    }
    CP_COMMIT();

    // load K tile 0 into stage 0 (slots 0,1)
#pragma unroll
    for (int i = 0; i < 2; i++) {
        int idx = tid + i * 256;
        int r = idx >> 3, c = idx & 7;
        cpa16(sb + KBASE + r * APB + c * 16, khg + idx * 16);
        cpa16(sb + KBASE + KT_B + r * APB + c * 16, klg + idx * 16);
    }
    CP_COMMIT();
    CP_WAIT(1);
    __syncthreads();

    // Q fragments (kept in regs for both passes)
    uint32_t qh[4][4], ql[4][4];
#pragma unroll
    for (int j = 0; j < 4; j++) {
        uint32_t r = wm * 16 + (lane & 7) + ((lane >> 3) & 1) * 8;
        uint32_t c = j * 16 + (lane >> 4) * 8;
        uint32_t off = r * APB + c * 2;
        ldsm4(qh[j], sb + off);
        ldsm4(ql[j], sb + QT_B + off);
    }

    const int r0g = qbase + wm * 16 + qr;
    const int r1g = r0g + 8;

    // ---------------- pass A: rowsums ----------------
    float rs0 = 0.f, rs1 = 0.f;
    for (int kt = 0; kt < nkt; kt++) {
        if (kt + 1 < nkt) {
            const uint32_t db = sb + KBASE + ((kt + 1) & 1) * KSTAGE;
            const long long go = (long long)(kt + 1) * 8192;
#pragma unroll
            for (int i = 0; i < 2; i++) {
                int idx = tid + i * 256;
                int r = idx >> 3, c = idx & 7;
                cpa16(db + r * APB + c * 16, khg + go + idx * 16);
                cpa16(db + KT_B + r * APB + c * 16, klg + go + idx * 16);
            }
            CP_COMMIT();
            CP_WAIT(1);
        } else {
            CP_WAIT(0);
        }
        __syncthreads();

        const uint32_t kb = sb + KBASE + (kt & 1) * KSTAGE;
#pragma unroll
        for (int nt = 0; nt < 8; nt++) {
            float s[4] = {0.f, 0.f, 0.f, 0.f};
#pragma unroll
            for (int j = 0; j < 4; j++) {
                uint32_t bh2[2], bl2[2];
                uint32_t n = nt * 8 + (lane & 7);
                uint32_t c = j * 16 + ((lane >> 3) & 1) * 8;
                uint32_t off = n * APB + c * 2;
                ldsm2(bh2, kb + off);
                ldsm2(bl2, kb + KT_B + off);
                mma_bf16(s, qh[j], bh2);
                mma_bf16(s, qh[j], bl2);
                mma_bf16(s, ql[j], bh2);
            }
            const int cg = kt * 64 + nt * 8 + qc2;
            if (cg <= r0g)     rs0 += __expf(s[0] * 0.125f);
            if (cg + 1 <= r0g) rs0 += __expf(s[1] * 0.125f);
            if (cg <= r1g)     rs1 += __expf(s[2] * 0.125f);
            if (cg + 1 <= r1g) rs1 += __expf(s[3] * 0.125f);
        }
        __syncthreads();
    }
    rs0 += __shfl_xor_sync(0xFFFFFFFFu, rs0, 1);
    rs0 += __shfl_xor_sync(0xFFFFFFFFu, rs0, 2);
    rs1 += __shfl_xor_sync(0xFFFFFFFFu, rs1, 1);
    rs1 += __shfl_xor_sync(0xFFFFFFFFu, rs1, 2);
    const float ri0 = 1.0f / rs0;
    const float ri1 = 1.0f / rs1;

    // ---------------- pass B: write attn + A@V ----------------
    float o[8][4];
#pragma unroll
    for (int a = 0; a < 8; a++)
#pragma unroll
        for (int c = 0; c < 4; c++) o[a][c] = 0.f;

    // restart pipeline: load K+V tile 0 into stage 0
#pragma unroll
    for (int i = 0; i < 2; i++) {
        int idx = tid + i * 256;
        int r = idx >> 3, c = idx & 7;
        uint32_t db = sb + KBASE;
        cpa16(db + r * APB + c * 16, khg + idx * 16);
        cpa16(db + KT_B + r * APB + c * 16, klg + idx * 16);
        cpa16(db + 2 * KT_B + r * APB + c * 16, vhg + idx * 16);
        cpa16(db + 3 * KT_B + r * APB + c * 16, vlg + idx * 16);
    }
    CP_COMMIT();

    for (int kt = 0; kt < nkt; kt++) {
        if (kt + 1 < nkt) {
            const uint32_t db = sb + KBASE + ((kt + 1) & 1) * KSTAGE;
            const long long go = (long long)(kt + 1) * 8192;
#pragma unroll
            for (int i = 0; i < 2; i++) {
                int idx = tid + i * 256;
                int r = idx >> 3, c = idx & 7;
                cpa16(db + r * APB + c * 16, khg + go + idx * 16);
                cpa16(db + KT_B + r * APB + c * 16, klg + go + idx * 16);
                cpa16(db + 2 * KT_B + r * APB + c * 16, vhg + go + idx * 16);
                cpa16(db + 3 * KT_B + r * APB + c * 16, vlg + go + idx * 16);
            }
            CP_COMMIT();
            CP_WAIT(1);
        } else {
            CP_WAIT(0);
        }
        __syncthreads();

        const uint32_t kb = sb + KBASE + (kt & 1) * KSTAGE;
        uint32_t sah[4][4], sal[4][4];
#pragma unroll
        for (int nt = 0; nt < 8; nt++) {
            float s[4] = {0.f, 0.f, 0.f, 0.f};
#pragma unroll
            for (int j = 0; j < 4; j++) {
                uint32_t bh2[2], bl2[2];
                uint32_t n = nt * 8 + (lane & 7);
                uint32_t c = j * 16 + ((lane >> 3) & 1) * 8;
                uint32_t off = n * APB + c * 2;
                ldsm2(bh2, kb + off);
                ldsm2(bl2, kb + KT_B + off);
                mma_bf16(s, qh[j], bh2);
                mma_bf16(s, qh[j], bl2);
                mma_bf16(s, ql[j], bh2);
            }
            const int cg = kt * 64 + nt * 8 + qc2;
            float e0 = (cg > r0g)     ? 0.f : __expf(s[0] * 0.125f) * ri0;
            float e1 = (cg + 1 > r0g) ? 0.f : __expf(s[1] * 0.125f) * ri0;
            float e2 = (cg > r1g)     ? 0.f : __expf(s[2] * 0.125f) * ri1;
            float e3 = (cg + 1 > r1g) ? 0.f : __expf(s[3] * 0.125f) * ri1;
            *(float2*)&attn_out[(long long)r0g * SS + cg] = make_float2(e0, e1);
            *(float2*)&attn_out[(long long)r1g * SS + cg] = make_float2(e2, e3);
            uint16_t h0, h1, h2, h3, l0, l1, l2, l3;
            sp(e0, h0, l0); sp(e1, h1, l1); sp(e2, h2, l2); sp(e3, h3, l3);
            const int j = nt >> 1, half = (nt & 1) * 2;
            sah[j][half] = pk(h0, h1); sah[j][half + 1] = pk(h2, h3);
            sal[j][half] = pk(l0, l1); sal[j][half + 1] = pk(l2, l3);
        }
#pragma unroll
        for (int j = 0; j < 4; j++) {
#pragma unroll
            for (int nt2 = 0; nt2 < 8; nt2++) {
                uint32_t vh2[2], vl2[2];
                uint32_t key = j * 16 + ((lane >> 3) & 1) * 8 + (lane & 7);
                uint32_t off = key * APB + nt2 * 16;
                ldsm2t(vh2, kb + 2 * KT_B + off);
                ldsm2t(vl2, kb + 3 * KT_B + off);
                mma_bf16(o[nt2], sah[j], vh2);
                mma_bf16(o[nt2], sah[j], vl2);
                mma_bf16(o[nt2], sal[j], vh2);
            }
        }
        __syncthreads();
    }

    // write merged-head output directly as bf16 hi/lo (feeds proj GEMM)
#pragma unroll
    for (int nt2 = 0; nt2 < 8; nt2++) {
        const int col = h * 64 + nt2 * 8 + qc2;
        const long long gr0 = (long long)(b * SS + qbase + wm * 16 + qr);
        uint16_t h0, h1, h2, h3, l0, l1, l2, l3;
        sp(o[nt2][0], h0, l0); sp(o[nt2][1], h1, l1);
        sp(o[nt2][2], h2, l2); sp(o[nt2][3], h3, l3);
        *(uint32_t*)&g_ahhi[gr0 * DD + col] = pk(h0, h1);
        *(uint32_t*)&g_ahlo[gr0 * DD + col] = pk(l0, l1);
        *(uint32_t*)&g_ahhi[(gr0 + 8) * DD + col] = pk(h2, h3);
        *(uint32_t*)&g_ahlo[(gr0 + 8) * DD + col] = pk(l2, l3);
    }
}

// ====================== upper-triangle zero fill ============================
__global__ __launch_bounds__(256) void attn_fill(float* __restrict__ out) {
    const int tid = threadIdx.x;
    const int qt = blockIdx.x, bh = blockIdx.y;
    const int Lc = (qt + 1) * 128;
    const int per4 = (SS - Lc) >> 2;
    if (per4 == 0) return;
    float* base = out + ATTN_OFF + (long long)bh * SS * SS + (long long)qt * 128 * SS;
    const float4 z = make_float4(0.f, 0.f, 0.f, 0.f);
    for (int i = tid; i < 128 * per4; i += 256) {
        int r = i / per4;
        int c = Lc + (i - r * per4) * 4;
        *(float4*)&base[(long long)r * SS + c] = z;
    }
}

// ====================== launch ==============================================
extern "C" void kernel_launch(void* const* d_in, const int* in_sizes, int n_in,
                              void* d_out, int out_size) {
    const float* x      = (const float*)d_in[0];
    const float* w_attn = (const float*)d_in[1];
    const float* b_attn = (const float*)d_in[2];
    const float* w_proj = (const float*)d_in[3];
    const float* b_proj = (const float*)d_in[4];
    float* out = (float*)d_out;

    __nv_bfloat16 *xhi, *xlo, *wahi, *walo, *wphi, *wplo, *ahhi, *ahlo;
    cudaGetSymbolAddress((void**)&xhi,  g_xhi);
    cudaGetSymbolAddress((void**)&xlo,  g_xlo);
    cudaGetSymbolAddress((void**)&wahi, g_wahi);
    cudaGetSymbolAddress((void**)&walo, g_walo);
    cudaGetSymbolAddress((void**)&wphi, g_wphi);
    cudaGetSymbolAddress((void**)&wplo, g_wplo);
    cudaGetSymbolAddress((void**)&ahhi, g_ahhi);
    cudaGetSymbolAddress((void**)&ahlo, g_ahlo);

    cudaFuncSetAttribute(gemm_mma<0>, cudaFuncAttributeMaxDynamicSharedMemorySize, GEMM_SMEM);
    cudaFuncSetAttribute(gemm_mma<1>, cudaFuncAttributeMaxDynamicSharedMemorySize, GEMM_SMEM);
    cudaFuncSetAttribute(attn_mma, cudaFuncAttributeMaxDynamicSharedMemorySize, ATTN_SMEM);

    // 0) split inputs (weights transposed to [N,K])
    split_plain<<<(MROWS * DD / 4 + 255) / 256, 256>>>(x, xhi, xlo, MROWS * DD / 4);
    split_T<<<dim3(N3 / 32, DD / 32), dim3(32, 8)>>>(w_attn, wahi, walo, N3);
    split_T<<<dim3(DD / 32, DD / 32), dim3(32, 8)>>>(w_proj, wphi, wplo, DD);

    // 1) QKV projection -> present(k,v) fp32 + q/k/v bf16 hi/lo scratch
    gemm_mma<0><<<dim3(N3 / 128, MROWS / 128), 256, GEMM_SMEM>>>(xhi, xlo, wahi, walo, b_attn, out);

    // 2) attention -> normalized attn region + ah hi/lo scratch
    attn_mma<<<dim3(SS / 128, HH, BB), 256, ATTN_SMEM>>>(out);

    // 3) zero-fill strictly-upper attn region
    attn_fill<<<dim3(SS / 128, BB * HH), 256>>>(out);

    // 4) output projection
    gemm_mma<1><<<dim3(DD / 128, MROWS / 128), 256, GEMM_SMEM>>>(ahhi, ahlo, wphi, wplo, b_proj, out);
}